// round 12
// baseline (speedup 1.0000x reference)
#include <cuda_runtime.h>
#include <cuda_fp16.h>
#include <cstdint>

#define NNODES 4000
#define NPAD   4096
#define BATCH  64
#define CIN    64
#define COUT   64
#define EMBD   10
#define JDIM   4096            // BATCH * CIN
#define KTILES 125             // 4000 / 32
#define BM     128
#define BN     256
#define BK     32              // halves per k-tile
#define PADHB  80              // smem row stride in BYTES (64B data + 16B pad; 16B-aligned)
#define A_STG  (BM * PADHB)    // 10240 B
#define STAGE_BYTES ((BM + BN) * PADHB)     // 30720 B
#define NSTAGE 4
#define GSMEM  (NSTAGE * STAGE_BYTES)       // 122880 B

// final_kernel shared layout (floats)
#define F_WS   0                      // [4][64][64]
#define F_XS   16384                  // [4][64][68]
#define F_BIAS 33792                  // [4][64]
#define F_EN   34048                  // [4][10]
#define F_TOT  34088
#define FSMEM  (F_TOT * 4)            // 136352 B

// Scratch (allocation-free rule: __device__ globals; zero-initialized at load)
__device__ __half g_Sh [(size_t)NPAD * NNODES];   // rows 4000..4095 stay zero forever
__device__ __half g_Xth[(size_t)JDIM * NNODES];   // x transposed fp16: [(b*64+c), m]
__device__ __half g_y1th[(size_t)JDIM * NNODES];  // y1 transposed fp16 (B of GEMM2)
__device__ float  g_y1n[(size_t)BATCH * NNODES * CIN];
__device__ float  g_y2n[(size_t)BATCH * NNODES * CIN];

// ---------------------------------------------------------------------------
// helpers
// ---------------------------------------------------------------------------
__device__ __forceinline__ uint32_t smem_u32(const void* p) {
    uint32_t a;
    asm("{ .reg .u64 t; cvta.to.shared.u64 t, %1; cvt.u32.u64 %0, t; }" : "=r"(a) : "l"(p));
    return a;
}
__device__ __forceinline__ void cp16(uint32_t dst, const void* src) {
    asm volatile("cp.async.cg.shared.global [%0], [%1], 16;" :: "r"(dst), "l"(src) : "memory");
}
#define CP_COMMIT() asm volatile("cp.async.commit_group;" ::: "memory")
#define CP_WAIT2()  asm volatile("cp.async.wait_group 2;" ::: "memory")

#define LDSM4(R, A) \
    asm volatile("ldmatrix.sync.aligned.m8n8.x4.shared.b16 {%0,%1,%2,%3}, [%4];" \
        : "=r"((R)[0]), "=r"((R)[1]), "=r"((R)[2]), "=r"((R)[3]) : "r"(A))

__device__ __forceinline__ void mma_f16(float* c, const uint32_t* a,
                                        uint32_t b0, uint32_t b1) {
    asm volatile(
        "mma.sync.aligned.m16n8k16.row.col.f32.f16.f16.f32 "
        "{%0,%1,%2,%3}, {%4,%5,%6,%7}, {%8,%9}, {%0,%1,%2,%3};"
        : "+f"(c[0]), "+f"(c[1]), "+f"(c[2]), "+f"(c[3])
        : "r"(a[0]), "r"(a[1]), "r"(a[2]), "r"(a[3]), "r"(b0), "r"(b1));
}

// ---------------------------------------------------------------------------
// Kernel 1: S = softmax(relu(E E^T), axis=1) -> fp16. One block per row.
// ---------------------------------------------------------------------------
__global__ __launch_bounds__(256) void supports_kernel(const float* __restrict__ emb) {
    __shared__ float logits[NNODES];
    __shared__ float en[EMBD];
    __shared__ float red[256];
    const int n = blockIdx.x;
    const int t = threadIdx.x;
    if (t < EMBD) en[t] = emb[n * EMBD + t];
    __syncthreads();

    float lmax = 0.0f;
    for (int m = t; m < NNODES; m += 256) {
        const float* em = emb + m * EMBD;
        float d = 0.f;
        #pragma unroll
        for (int i = 0; i < EMBD; i++) d += en[i] * em[i];
        d = fmaxf(d, 0.f);
        logits[m] = d;
        lmax = fmaxf(lmax, d);
    }
    red[t] = lmax; __syncthreads();
    for (int s = 128; s > 0; s >>= 1) {
        if (t < s) red[t] = fmaxf(red[t], red[t + s]);
        __syncthreads();
    }
    const float mx = red[0];
    __syncthreads();

    float lsum = 0.f;
    for (int m = t; m < NNODES; m += 256) {
        float e = __expf(logits[m] - mx);
        logits[m] = e;
        lsum += e;
    }
    red[t] = lsum; __syncthreads();
    for (int s = 128; s > 0; s >>= 1) {
        if (t < s) red[t] += red[t + s];
        __syncthreads();
    }
    const float inv = 1.0f / red[0];
    __half* Srow = g_Sh + (size_t)n * NNODES;
    for (int m = t; m < NNODES; m += 256) Srow[m] = __float2half_rn(logits[m] * inv);
}

// ---------------------------------------------------------------------------
// Kernel 2: transpose x[b,m,c] -> Xth[(b*64+c), m] fp16
// ---------------------------------------------------------------------------
__global__ __launch_bounds__(256) void transpose_kernel(const float* __restrict__ x) {
    __shared__ float Ts[128][68];
    const int t  = threadIdx.x;
    const int m0 = blockIdx.x * 128;
    const int b  = blockIdx.y;

    #pragma unroll
    for (int i = 0; i < 8; i++) {
        const int idx = t + 256 * i;
        const int row = idx >> 4, c4 = idx & 15;
        float4 v = make_float4(0.f, 0.f, 0.f, 0.f);
        if (m0 + row < NNODES)
            v = *(const float4*)&x[((size_t)b * NNODES + m0 + row) * CIN + c4 * 4];
        *(float4*)&Ts[row][c4 * 4] = v;
    }
    __syncthreads();

    #pragma unroll
    for (int i = 0; i < 8; i++) {
        const int o  = t + 256 * i;
        const int c  = o >> 5, mk = o & 31;
        const int m  = m0 + mk * 4;
        if (m + 3 < NNODES) {
            __half2 p0 = __floats2half2_rn(Ts[mk*4+0][c], Ts[mk*4+1][c]);
            __half2 p1 = __floats2half2_rn(Ts[mk*4+2][c], Ts[mk*4+3][c]);
            __half* dst = &g_Xth[(size_t)(b * 64 + c) * NNODES + m];
            *(__half2*)(dst)     = p0;
            *(__half2*)(dst + 2) = p1;
        }
    }
}

// ---------------------------------------------------------------------------
// Kernel 3: fp16 mma.sync GEMM  C[128,256] = S_tile[128,4000] @ B_tile^T
//   PHASE 0: B = Xth,  outputs y1n + y1th
//   PHASE 1: B = y1th, outputs y2n
// 8 warps as 2(M) x 4(N); warp tile 64x64; 4-stage cp.async, ldmatrix frags.
// ---------------------------------------------------------------------------
template <int PHASE>
__global__ __launch_bounds__(256, 1) void gemm_mma() {
    extern __shared__ char sm[];
    const uint32_t sBase = smem_u32(sm);

    const __half* __restrict__ Bmat = (PHASE == 0) ? g_Xth : g_y1th;
    const int m0 = blockIdx.x * BM;
    const int j0 = blockIdx.y * BN;

    const int t    = threadIdx.x;
    const int lane = t & 31, warp = t >> 5;
    const int wm = warp >> 2, wn = warp & 3;
    const int g = lane >> 2, tig = lane & 3;

    const int lr = t >> 2, lq = t & 3;   // load map: 64 rows x 4 x 16B per pass

    // ldmatrix per-lane base offsets (bytes within a stage)
    //  A x4: r0=(rows+0,kLo) r1=(rows+8,kLo) r2=(rows+0,kHi) r3=(rows+8,kHi)
    const uint32_t aOff = (uint32_t)((wm * 64 + (lane & 7) + ((lane >> 3) & 1) * 8) * PADHB
                                     + ((lane >> 4) & 1) * 16);
    //  B x4: r0=(n0-7,kLo) r1=(n0-7,kHi) r2=(n8-15,kLo) r3=(n8-15,kHi)
    const uint32_t bOff = (uint32_t)(A_STG
                                     + (wn * 64 + (lane & 7) + ((lane >> 4) & 1) * 8) * PADHB
                                     + ((lane >> 3) & 1) * 16);

    float acc[4][8][4];
    #pragma unroll
    for (int mi = 0; mi < 4; mi++)
        #pragma unroll
        for (int ni = 0; ni < 8; ni++)
            #pragma unroll
            for (int q = 0; q < 4; q++) acc[mi][ni][q] = 0.f;

    auto load_tile = [&](int kt, int s) {
        const size_t kc = (size_t)kt * BK;           // in halves
        const uint32_t st = sBase + s * STAGE_BYTES;
        #pragma unroll
        for (int i = 0; i < 2; i++) {
            const int r = lr + 64 * i;               // 0..127
            cp16(st + r * PADHB + lq * 16,
                 g_Sh + (size_t)(m0 + r) * NNODES + kc + lq * 8);
        }
        #pragma unroll
        for (int i = 0; i < 4; i++) {
            const int r = lr + 64 * i;               // 0..255
            cp16(st + A_STG + r * PADHB + lq * 16,
                 Bmat + (size_t)(j0 + r) * NNODES + kc + lq * 8);
        }
    };

    load_tile(0, 0); CP_COMMIT();
    load_tile(1, 1); CP_COMMIT();
    load_tile(2, 2); CP_COMMIT();

    int sc = 0;           // compute slot
    int sl = 3;           // load slot (for kt+3)
    for (int kt = 0; kt < KTILES; ++kt) {
        CP_WAIT2();                       // stage kt resident (≤2 groups in flight)
        __syncthreads();

        const uint32_t st = sBase + sc * STAGE_BYTES;
        #pragma unroll
        for (int k16 = 0; k16 < 2; ++k16) {
            uint32_t a[4][4], b[4][4];
            #pragma unroll
            for (int mi = 0; mi < 4; mi++)
                LDSM4(a[mi], st + aOff + mi * (16 * PADHB) + k16 * 32);
            #pragma unroll
            for (int nb = 0; nb < 4; nb++)
                LDSM4(b[nb], st + bOff + nb * (16 * PADHB) + k16 * 32);
            #pragma unroll
            for (int mi = 0; mi < 4; mi++)
                #pragma unroll
                for (int nb = 0; nb < 4; nb++) {
                    mma_f16(acc[mi][nb * 2 + 0], a[mi], b[nb][0], b[nb][1]);
                    mma_f16(acc[mi][nb * 2 + 1], a[mi], b[nb][2], b[nb][3]);
                }
        }

        if (kt + 3 < KTILES) load_tile(kt + 3, sl);
        CP_COMMIT();                      // uniform group count (empty groups OK)
        if (++sc == NSTAGE) sc = 0;
        if (++sl == NSTAGE) sl = 0;
    }

    // ---- epilogue: write y*n normal layout (+ y1th transposed for GEMM2)
    float* __restrict__ outn = (PHASE == 0) ? g_y1n : g_y2n;
    #pragma unroll
    for (int mi = 0; mi < 4; mi++) {
        const int m = m0 + wm * 64 + mi * 16 + g;
        #pragma unroll
        for (int ni = 0; ni < 8; ni++) {
            const float* c = acc[mi][ni];
            const int j = j0 + wn * 64 + ni * 8 + tig * 2;
            const int b = j >> 6, cc = j & 63;
            if (m < NNODES) {
                *(float2*)&outn[((size_t)b * NNODES + m) * CIN + cc] = make_float2(c[0], c[1]);
                if (PHASE == 0) {
                    g_y1th[(size_t)j * NNODES + m]       = __float2half_rn(c[0]);
                    g_y1th[(size_t)(j + 1) * NNODES + m] = __float2half_rn(c[1]);
                }
            }
            const int m2 = m + 8;
            if (m2 < NNODES) {
                *(float2*)&outn[((size_t)b * NNODES + m2) * CIN + cc] = make_float2(c[2], c[3]);
                if (PHASE == 0) {
                    g_y1th[(size_t)j * NNODES + m2]       = __float2half_rn(c[2]);
                    g_y1th[(size_t)(j + 1) * NNODES + m2] = __float2half_rn(c[3]);
                }
            }
        }
    }
}

// ---------------------------------------------------------------------------
// Kernel 4: out[b,n,o] = sum_{k,i} xg_k[b,n,i] * W_k[n,i,o] + bias[n,o]
//   xg_0 = x, xg_1 = y1, xg_2 = 2*y2 - x
// 4 nodes per block, 512 threads; per node 128 threads do 4(b) x 8(o) each.
// wp float4 loads shared across the 4 nodes (4x less L2 traffic).
// ---------------------------------------------------------------------------
__global__ __launch_bounds__(512) void final_kernel(const float* __restrict__ x,
                                                    const float* __restrict__ emb,
                                                    const float* __restrict__ wp,
                                                    const float* __restrict__ bp,
                                                    float* __restrict__ out) {
    extern __shared__ float fsm[];
    float* Ws    = fsm + F_WS;     // [4][64][64]
    float* Xs    = fsm + F_XS;     // [4][64][68]
    float* bias4 = fsm + F_BIAS;   // [4][64]
    float* en4   = fsm + F_EN;     // [4][10]

    const int t  = threadIdx.x;
    const int n0 = blockIdx.x * 4;

    if (t < 4 * EMBD) en4[t] = emb[(n0 + t / EMBD) * EMBD + (t % EMBD)];
    __syncthreads();
    if (t < 256) {
        const int nd = t >> 6, o = t & 63;
        float s = 0.f;
        #pragma unroll
        for (int d = 0; d < EMBD; d++) s += en4[nd * EMBD + d] * bp[d * COUT + o];
        bias4[nd * 64 + o] = s;
    }
    __syncthreads();

    const int node = t >> 7, wt = t & 127;
    const int ob = (wt & 7) * 8;          // 8 consecutive outputs
    const int bb = (wt >> 3) * 4;         // 4 batches

    float acc[4][8];
    #pragma unroll
    for (int bi = 0; bi < 4; bi++)
        #pragma unroll
        for (int oi = 0; oi < 8; oi++) acc[bi][oi] = bias4[node * 64 + ob + oi];

    for (int k = 0; k < 3; k++) {
        __syncthreads();   // previous phase's shared reads done

        // generate per-node weights for all 4 nodes, sharing wp loads
        #pragma unroll
        for (int j = 0; j < 2; j++) {
            const int q  = t + 512 * j;        // 1024 (i,o4) slots
            const int i  = q >> 4;
            const int o4 = (q & 15) * 4;
            float4 w[4];
            #pragma unroll
            for (int nd = 0; nd < 4; nd++) w[nd] = make_float4(0.f, 0.f, 0.f, 0.f);
            #pragma unroll
            for (int d = 0; d < EMBD; d++) {
                const float4 wv = *(const float4*)&wp[(((d * 3 + k) * CIN + i) * COUT) + o4];
                #pragma unroll
                for (int nd = 0; nd < 4; nd++) {
                    const float ed = en4[nd * EMBD + d];
                    w[nd].x += ed * wv.x; w[nd].y += ed * wv.y;
                    w[nd].z += ed * wv.z; w[nd].w += ed * wv.w;
                }
            }
            #pragma unroll
            for (int nd = 0; nd < 4; nd++)
                *(float4*)&Ws[nd * 4096 + i * 64 + o4] = w[nd];
        }

        // load xg_k rows for all 4 nodes x 64 batches
        #pragma unroll
        for (int j = 0; j < 8; j++) {
            const int q  = t + 512 * j;        // 4096 slots
            const int nd = q >> 10;
            const int r  = q & 1023;
            const int b  = r >> 4;
            const int c4 = (r & 15) * 4;
            const size_t off = ((size_t)b * NNODES + n0 + nd) * CIN + c4;
            float4 v;
            if (k == 0)      v = *(const float4*)&x[off];
            else if (k == 1) v = *(const float4*)&g_y1n[off];
            else {
                const float4 v2 = *(const float4*)&g_y2n[off];
                const float4 vx = *(const float4*)&x[off];
                v = make_float4(2.f * v2.x - vx.x, 2.f * v2.y - vx.y,
                                2.f * v2.z - vx.z, 2.f * v2.w - vx.w);
            }
            *(float4*)&Xs[nd * 4352 + b * 68 + c4] = v;
        }
        __syncthreads();

        #pragma unroll 8
        for (int i = 0; i < CIN; i++) {
            const float4 w0 = *(const float4*)&Ws[node * 4096 + i * 64 + ob];
            const float4 w1 = *(const float4*)&Ws[node * 4096 + i * 64 + ob + 4];
            float xr[4];
            #pragma unroll
            for (int bi = 0; bi < 4; bi++) xr[bi] = Xs[node * 4352 + (bb + bi) * 68 + i];
            #pragma unroll
            for (int bi = 0; bi < 4; bi++) {
                acc[bi][0] += xr[bi] * w0.x;
                acc[bi][1] += xr[bi] * w0.y;
                acc[bi][2] += xr[bi] * w0.z;
                acc[bi][3] += xr[bi] * w0.w;
                acc[bi][4] += xr[bi] * w1.x;
                acc[bi][5] += xr[bi] * w1.y;
                acc[bi][6] += xr[bi] * w1.z;
                acc[bi][7] += xr[bi] * w1.w;
            }
        }
    }

    #pragma unroll
    for (int bi = 0; bi < 4; bi++) {
        const size_t off = ((size_t)(bb + bi) * NNODES + n0 + node) * COUT + ob;
        *(float4*)&out[off]     = make_float4(acc[bi][0], acc[bi][1], acc[bi][2], acc[bi][3]);
        *(float4*)&out[off + 4] = make_float4(acc[bi][4], acc[bi][5], acc[bi][6], acc[bi][7]);
    }
}

// ---------------------------------------------------------------------------
extern "C" void kernel_launch(void* const* d_in, const int* in_sizes, int n_in,
                              void* d_out, int out_size) {
    const float* x   = (const float*)d_in[0];   // [B, N, CIN]
    const float* emb = (const float*)d_in[1];   // [N, D]
    const float* wp  = (const float*)d_in[2];   // [D, K, CIN, COUT]
    const float* bp  = (const float*)d_in[3];   // [D, COUT]
    float* out = (float*)d_out;                 // [B, N, COUT]

    cudaFuncSetAttribute(gemm_mma<0>, cudaFuncAttributeMaxDynamicSharedMemorySize, GSMEM);
    cudaFuncSetAttribute(gemm_mma<1>, cudaFuncAttributeMaxDynamicSharedMemorySize, GSMEM);
    cudaFuncSetAttribute(final_kernel, cudaFuncAttributeMaxDynamicSharedMemorySize, FSMEM);

    supports_kernel<<<NNODES, 256>>>(emb);
    transpose_kernel<<<dim3(32, BATCH), 256>>>(x);

    dim3 g(32, 16);                             // Mtiles x Ntiles
    gemm_mma<0><<<g, 256, GSMEM>>>();           // y1 = S @ x   (-> y1n, y1th)
    gemm_mma<1><<<g, 256, GSMEM>>>();           // y2 = S @ y1  (-> y2n)

    final_kernel<<<NNODES / 4, 512, FSMEM>>>(x, emb, wp, bp, out);
}

// round 13
// speedup vs baseline: 1.1434x; 1.1434x over previous
#include <cuda_runtime.h>
#include <cuda_fp16.h>
#include <cstdint>

#define NNODES 4000
#define NPAD   4096
#define BATCH  64
#define CIN    64
#define COUT   64
#define EMBD   10
#define JDIM   4096            // BATCH * CIN
#define KTILES 125             // 4000 / 32
#define BM     128
#define BN     128
#define BK     32              // halves per k-tile
#define PADHB  80              // smem row stride in BYTES (64B data + 16B pad)
#define A_STG  (BM * PADHB)    // 10240 B
#define STAGE_BYTES ((BM + BN) * PADHB)     // 20480 B
#define NSTAGE 5
#define GSMEM  (NSTAGE * STAGE_BYTES)       // 102400 B

// final_kernel shared layout (floats): 2 nodes per block
#define F_WS   0                      // [2][64][64]
#define F_XS   8192                   // [2][64][68]
#define F_BIAS 16896                  // [2][64]
#define F_EN   17024                  // [2][10]
#define F_TOT  17044
#define FSMEM  (F_TOT * 4)            // 68176 B

// Scratch (allocation-free rule: __device__ globals; zero-initialized at load)
__device__ __half g_Sh [(size_t)NPAD * NNODES];   // rows 4000..4095 stay zero forever
__device__ __half g_Xth[(size_t)JDIM * NNODES];   // x transposed fp16: [(b*64+c), m]
__device__ __half g_y1th[(size_t)JDIM * NNODES];  // y1 transposed fp16 (B of GEMM2)
__device__ float  g_y1n[(size_t)BATCH * NNODES * CIN];
__device__ float  g_y2n[(size_t)BATCH * NNODES * CIN];

// ---------------------------------------------------------------------------
// helpers
// ---------------------------------------------------------------------------
__device__ __forceinline__ uint32_t smem_u32(const void* p) {
    uint32_t a;
    asm("{ .reg .u64 t; cvta.to.shared.u64 t, %1; cvt.u32.u64 %0, t; }" : "=r"(a) : "l"(p));
    return a;
}
__device__ __forceinline__ void cp16(uint32_t dst, const void* src) {
    asm volatile("cp.async.cg.shared.global [%0], [%1], 16;" :: "r"(dst), "l"(src) : "memory");
}
#define CP_COMMIT() asm volatile("cp.async.commit_group;" ::: "memory")
#define CP_WAIT3()  asm volatile("cp.async.wait_group 3;" ::: "memory")

#define LDSM4(R, A) \
    asm volatile("ldmatrix.sync.aligned.m8n8.x4.shared.b16 {%0,%1,%2,%3}, [%4];" \
        : "=r"((R)[0]), "=r"((R)[1]), "=r"((R)[2]), "=r"((R)[3]) : "r"(A))

__device__ __forceinline__ void mma_f16(float* c, const uint32_t* a,
                                        uint32_t b0, uint32_t b1) {
    asm volatile(
        "mma.sync.aligned.m16n8k16.row.col.f32.f16.f16.f32 "
        "{%0,%1,%2,%3}, {%4,%5,%6,%7}, {%8,%9}, {%0,%1,%2,%3};"
        : "+f"(c[0]), "+f"(c[1]), "+f"(c[2]), "+f"(c[3])
        : "r"(a[0]), "r"(a[1]), "r"(a[2]), "r"(a[3]), "r"(b0), "r"(b1));
}

// ---------------------------------------------------------------------------
// Kernel 1: S = softmax(relu(E E^T), axis=1) -> fp16. 4 rows per block:
// each em row load is shared across 4 output rows (4x less emb L2 traffic).
// ---------------------------------------------------------------------------
__global__ __launch_bounds__(256) void supports_kernel(const float* __restrict__ emb) {
    extern __shared__ float ssm[];          // logits[4][NNODES]
    __shared__ float en4[4][EMBD];
    __shared__ float red4[4][256];
    const int n0 = blockIdx.x * 4;
    const int t = threadIdx.x;
    if (t < 4 * EMBD) en4[t / EMBD][t % EMBD] = emb[(n0 + t / EMBD) * EMBD + (t % EMBD)];
    __syncthreads();

    float lmax[4] = {0.f, 0.f, 0.f, 0.f};   // relu => >= 0
    for (int m = t; m < NNODES; m += 256) {
        float em[EMBD];
        #pragma unroll
        for (int i = 0; i < EMBD; i++) em[i] = emb[m * EMBD + i];
        #pragma unroll
        for (int r = 0; r < 4; r++) {
            float d = 0.f;
            #pragma unroll
            for (int i = 0; i < EMBD; i++) d += en4[r][i] * em[i];
            d = fmaxf(d, 0.f);
            ssm[r * NNODES + m] = d;
            lmax[r] = fmaxf(lmax[r], d);
        }
    }
    #pragma unroll
    for (int r = 0; r < 4; r++) red4[r][t] = lmax[r];
    __syncthreads();
    for (int s = 128; s > 0; s >>= 1) {
        if (t < s)
            #pragma unroll
            for (int r = 0; r < 4; r++) red4[r][t] = fmaxf(red4[r][t], red4[r][t + s]);
        __syncthreads();
    }
    float mx[4];
    #pragma unroll
    for (int r = 0; r < 4; r++) mx[r] = red4[r][0];
    __syncthreads();

    float lsum[4] = {0.f, 0.f, 0.f, 0.f};
    for (int m = t; m < NNODES; m += 256) {
        #pragma unroll
        for (int r = 0; r < 4; r++) {
            float e = __expf(ssm[r * NNODES + m] - mx[r]);
            ssm[r * NNODES + m] = e;
            lsum[r] += e;
        }
    }
    #pragma unroll
    for (int r = 0; r < 4; r++) red4[r][t] = lsum[r];
    __syncthreads();
    for (int s = 128; s > 0; s >>= 1) {
        if (t < s)
            #pragma unroll
            for (int r = 0; r < 4; r++) red4[r][t] += red4[r][t + s];
        __syncthreads();
    }
    float inv[4];
    #pragma unroll
    for (int r = 0; r < 4; r++) inv[r] = 1.0f / red4[r][0];

    for (int m = t; m < NNODES; m += 256) {
        #pragma unroll
        for (int r = 0; r < 4; r++)
            g_Sh[(size_t)(n0 + r) * NNODES + m] = __float2half_rn(ssm[r * NNODES + m] * inv[r]);
    }
}

// ---------------------------------------------------------------------------
// Kernel 2: transpose x[b,m,c] -> Xth[(b*64+c), m] fp16
// ---------------------------------------------------------------------------
__global__ __launch_bounds__(256) void transpose_kernel(const float* __restrict__ x) {
    __shared__ float Ts[128][68];
    const int t  = threadIdx.x;
    const int m0 = blockIdx.x * 128;
    const int b  = blockIdx.y;

    #pragma unroll
    for (int i = 0; i < 8; i++) {
        const int idx = t + 256 * i;
        const int row = idx >> 4, c4 = idx & 15;
        float4 v = make_float4(0.f, 0.f, 0.f, 0.f);
        if (m0 + row < NNODES)
            v = *(const float4*)&x[((size_t)b * NNODES + m0 + row) * CIN + c4 * 4];
        *(float4*)&Ts[row][c4 * 4] = v;
    }
    __syncthreads();

    #pragma unroll
    for (int i = 0; i < 8; i++) {
        const int o  = t + 256 * i;
        const int c  = o >> 5, mk = o & 31;
        const int m  = m0 + mk * 4;
        if (m + 3 < NNODES) {
            __half2 p0 = __floats2half2_rn(Ts[mk*4+0][c], Ts[mk*4+1][c]);
            __half2 p1 = __floats2half2_rn(Ts[mk*4+2][c], Ts[mk*4+3][c]);
            __half* dst = &g_Xth[(size_t)(b * 64 + c) * NNODES + m];
            *(__half2*)(dst)     = p0;
            *(__half2*)(dst + 2) = p1;
        }
    }
}

// ---------------------------------------------------------------------------
// Kernel 3: fp16 mma.sync GEMM  C[128,128] = S_tile[128,4000] @ B_tile^T
//   PHASE 0: B = Xth,  outputs y1n + y1th
//   PHASE 1: B = y1th, outputs y2n
// 8 warps as 2(M) x 4(N); warp tile 64x32; 5-stage cp.async; loads issued
// between the first LDSM batch and its MMAs to overlap LDGSTS with tensor.
// ---------------------------------------------------------------------------
template <int PHASE>
__global__ __launch_bounds__(256, 2) void gemm_mma() {
    extern __shared__ char sm[];
    const uint32_t sBase = smem_u32(sm);

    const __half* __restrict__ Bmat = (PHASE == 0) ? g_Xth : g_y1th;
    const int m0 = blockIdx.x * BM;
    const int j0 = blockIdx.y * BN;

    const int t    = threadIdx.x;
    const int lane = t & 31, warp = t >> 5;
    const int wm = warp >> 2, wn = warp & 3;
    const int g = lane >> 2, tig = lane & 3;

    const int lr = t >> 2, lq = t & 3;   // load map: 64 rows x 4 x 16B per pass

    //  A x4: r0=(rows+0,kLo) r1=(rows+8,kLo) r2=(rows+0,kHi) r3=(rows+8,kHi)
    const uint32_t aOff = (uint32_t)((wm * 64 + (lane & 7) + ((lane >> 3) & 1) * 8) * PADHB
                                     + ((lane >> 4) & 1) * 16);
    //  B x4: r0=(n0-7,kLo) r1=(n0-7,kHi) r2=(n8-15,kLo) r3=(n8-15,kHi)
    const uint32_t bOff = (uint32_t)(A_STG
                                     + (wn * 32 + (lane & 7) + ((lane >> 4) & 1) * 8) * PADHB
                                     + ((lane >> 3) & 1) * 16);

    float acc[4][4][4];
    #pragma unroll
    for (int mi = 0; mi < 4; mi++)
        #pragma unroll
        for (int ni = 0; ni < 4; ni++)
            #pragma unroll
            for (int q = 0; q < 4; q++) acc[mi][ni][q] = 0.f;

    auto load_tile = [&](int kt, int s) {
        const size_t kc = (size_t)kt * BK;           // in halves
        const uint32_t st = sBase + s * STAGE_BYTES;
        #pragma unroll
        for (int i = 0; i < 2; i++) {
            const int r = lr + 64 * i;               // 0..127
            cp16(st + r * PADHB + lq * 16,
                 g_Sh + (size_t)(m0 + r) * NNODES + kc + lq * 8);
            cp16(st + A_STG + r * PADHB + lq * 16,
                 Bmat + (size_t)(j0 + r) * NNODES + kc + lq * 8);
        }
    };

    load_tile(0, 0); CP_COMMIT();
    load_tile(1, 1); CP_COMMIT();
    load_tile(2, 2); CP_COMMIT();
    load_tile(3, 3); CP_COMMIT();

    int sc = 0;           // compute slot
    int sl = 4;           // load slot (for kt+4)
    for (int kt = 0; kt < KTILES; ++kt) {
        CP_WAIT3();                       // stage kt resident (≤3 groups in flight)
        __syncthreads();

        const uint32_t st = sBase + sc * STAGE_BYTES;
        {   // ---- k16 = 0: LDSM, then issue next gmem loads, then MMA
            uint32_t a[4][4], b[2][4];
            #pragma unroll
            for (int mi = 0; mi < 4; mi++)
                LDSM4(a[mi], st + aOff + mi * (16 * PADHB));
            LDSM4(b[0], st + bOff);
            LDSM4(b[1], st + bOff + 16 * PADHB);

            if (kt + 4 < KTILES) load_tile(kt + 4, sl);
            CP_COMMIT();                  // uniform group count (empty groups OK)

            #pragma unroll
            for (int mi = 0; mi < 4; mi++) {
                mma_f16(acc[mi][0], a[mi], b[0][0], b[0][1]);
                mma_f16(acc[mi][1], a[mi], b[0][2], b[0][3]);
                mma_f16(acc[mi][2], a[mi], b[1][0], b[1][1]);
                mma_f16(acc[mi][3], a[mi], b[1][2], b[1][3]);
            }
        }
        {   // ---- k16 = 1
            uint32_t a[4][4], b[2][4];
            #pragma unroll
            for (int mi = 0; mi < 4; mi++)
                LDSM4(a[mi], st + aOff + mi * (16 * PADHB) + 32);
            LDSM4(b[0], st + bOff + 32);
            LDSM4(b[1], st + bOff + 16 * PADHB + 32);
            #pragma unroll
            for (int mi = 0; mi < 4; mi++) {
                mma_f16(acc[mi][0], a[mi], b[0][0], b[0][1]);
                mma_f16(acc[mi][1], a[mi], b[0][2], b[0][3]);
                mma_f16(acc[mi][2], a[mi], b[1][0], b[1][1]);
                mma_f16(acc[mi][3], a[mi], b[1][2], b[1][3]);
            }
        }

        if (++sc == NSTAGE) sc = 0;
        if (++sl == NSTAGE) sl = 0;
    }

    // ---- epilogue: write y*n normal layout (+ y1th transposed for GEMM2)
    float* __restrict__ outn = (PHASE == 0) ? g_y1n : g_y2n;
    #pragma unroll
    for (int mi = 0; mi < 4; mi++) {
        const int m = m0 + wm * 64 + mi * 16 + g;
        #pragma unroll
        for (int ni = 0; ni < 4; ni++) {
            const float* c = acc[mi][ni];
            const int j = j0 + wn * 32 + ni * 8 + tig * 2;
            const int b = j >> 6, cc = j & 63;
            if (m < NNODES) {
                *(float2*)&outn[((size_t)b * NNODES + m) * CIN + cc] = make_float2(c[0], c[1]);
                if (PHASE == 0) {
                    g_y1th[(size_t)j * NNODES + m]       = __float2half_rn(c[0]);
                    g_y1th[(size_t)(j + 1) * NNODES + m] = __float2half_rn(c[1]);
                }
            }
            const int m2 = m + 8;
            if (m2 < NNODES) {
                *(float2*)&outn[((size_t)b * NNODES + m2) * CIN + cc] = make_float2(c[2], c[3]);
                if (PHASE == 0) {
                    g_y1th[(size_t)j * NNODES + m2]       = __float2half_rn(c[2]);
                    g_y1th[(size_t)(j + 1) * NNODES + m2] = __float2half_rn(c[3]);
                }
            }
        }
    }
}

// ---------------------------------------------------------------------------
// Kernel 4: out[b,n,o] = sum_{k,i} xg_k[b,n,i] * W_k[n,i,o] + bias[n,o]
//   xg_0 = x, xg_1 = y1, xg_2 = 2*y2 - x
// 2 nodes per block, 256 threads (smem 68KB -> 3 blocks/SM); per node
// 128 threads do 4(b) x 8(o) each; wp loads shared across the 2 nodes.
// ---------------------------------------------------------------------------
__global__ __launch_bounds__(256) void final_kernel(const float* __restrict__ x,
                                                    const float* __restrict__ emb,
                                                    const float* __restrict__ wp,
                                                    const float* __restrict__ bp,
                                                    float* __restrict__ out) {
    extern __shared__ float fsm[];
    float* Ws    = fsm + F_WS;     // [2][64][64]
    float* Xs    = fsm + F_XS;     // [2][64][68]
    float* bias2 = fsm + F_BIAS;   // [2][64]
    float* en2   = fsm + F_EN;     // [2][10]

    const int t  = threadIdx.x;
    const int n0 = blockIdx.x * 2;

    if (t < 2 * EMBD) en2[t] = emb[(n0 + t / EMBD) * EMBD + (t % EMBD)];
    __syncthreads();
    if (t < 128) {
        const int nd = t >> 6, o = t & 63;
        float s = 0.f;
        #pragma unroll
        for (int d = 0; d < EMBD; d++) s += en2[nd * EMBD + d] * bp[d * COUT + o];
        bias2[nd * 64 + o] = s;
    }
    __syncthreads();

    const int node = t >> 7, wt = t & 127;
    const int ob = (wt & 7) * 8;          // 8 consecutive outputs
    const int bb = (wt >> 3) * 4;         // 4 batches

    float acc[4][8];
    #pragma unroll
    for (int bi = 0; bi < 4; bi++)
        #pragma unroll
        for (int oi = 0; oi < 8; oi++) acc[bi][oi] = bias2[node * 64 + ob + oi];

    for (int k = 0; k < 3; k++) {
        __syncthreads();   // previous phase's shared reads done

        // generate per-node weights for both nodes, sharing wp loads
        #pragma unroll
        for (int j = 0; j < 4; j++) {
            const int q  = t + 256 * j;        // 1024 (i,o4) slots
            const int i  = q >> 4;
            const int o4 = (q & 15) * 4;
            float4 w0 = make_float4(0.f, 0.f, 0.f, 0.f);
            float4 w1 = make_float4(0.f, 0.f, 0.f, 0.f);
            #pragma unroll
            for (int d = 0; d < EMBD; d++) {
                const float4 wv = *(const float4*)&wp[(((d * 3 + k) * CIN + i) * COUT) + o4];
                const float e0 = en2[d], e1 = en2[EMBD + d];
                w0.x += e0 * wv.x; w0.y += e0 * wv.y; w0.z += e0 * wv.z; w0.w += e0 * wv.w;
                w1.x += e1 * wv.x; w1.y += e1 * wv.y; w1.z += e1 * wv.z; w1.w += e1 * wv.w;
            }
            *(float4*)&Ws[i * 64 + o4]        = w0;
            *(float4*)&Ws[4096 + i * 64 + o4] = w1;
        }

        // load xg_k rows for both nodes x 64 batches
        #pragma unroll
        for (int j = 0; j < 8; j++) {
            const int q  = t + 256 * j;        // 2048 slots
            const int nd = q >> 10;
            const int r  = q & 1023;
            const int b  = r >> 4;
            const int c4 = (r & 15) * 4;
            const size_t off = ((size_t)b * NNODES + n0 + nd) * CIN + c4;
            float4 v;
            if (k == 0)      v = *(const float4*)&x[off];
            else if (k == 1) v = *(const float4*)&g_y1n[off];
            else {
                const float4 v2 = *(const float4*)&g_y2n[off];
                const float4 vx = *(const float4*)&x[off];
                v = make_float4(2.f * v2.x - vx.x, 2.f * v2.y - vx.y,
                                2.f * v2.z - vx.z, 2.f * v2.w - vx.w);
            }
            *(float4*)&Xs[nd * 4352 + b * 68 + c4] = v;
        }
        __syncthreads();

        #pragma unroll 8
        for (int i = 0; i < CIN; i++) {
            const float4 w0 = *(const float4*)&Ws[node * 4096 + i * 64 + ob];
            const float4 w1 = *(const float4*)&Ws[node * 4096 + i * 64 + ob + 4];
            float xr[4];
            #pragma unroll
            for (int bi = 0; bi < 4; bi++) xr[bi] = Xs[node * 4352 + (bb + bi) * 68 + i];
            #pragma unroll
            for (int bi = 0; bi < 4; bi++) {
                acc[bi][0] += xr[bi] * w0.x;
                acc[bi][1] += xr[bi] * w0.y;
                acc[bi][2] += xr[bi] * w0.z;
                acc[bi][3] += xr[bi] * w0.w;
                acc[bi][4] += xr[bi] * w1.x;
                acc[bi][5] += xr[bi] * w1.y;
                acc[bi][6] += xr[bi] * w1.z;
                acc[bi][7] += xr[bi] * w1.w;
            }
        }
    }

    #pragma unroll
    for (int bi = 0; bi < 4; bi++) {
        const size_t off = ((size_t)(bb + bi) * NNODES + n0 + node) * COUT + ob;
        *(float4*)&out[off]     = make_float4(acc[bi][0], acc[bi][1], acc[bi][2], acc[bi][3]);
        *(float4*)&out[off + 4] = make_float4(acc[bi][4], acc[bi][5], acc[bi][6], acc[bi][7]);
    }
}

// ---------------------------------------------------------------------------
extern "C" void kernel_launch(void* const* d_in, const int* in_sizes, int n_in,
                              void* d_out, int out_size) {
    const float* x   = (const float*)d_in[0];   // [B, N, CIN]
    const float* emb = (const float*)d_in[1];   // [N, D]
    const float* wp  = (const float*)d_in[2];   // [D, K, CIN, COUT]
    const float* bp  = (const float*)d_in[3];   // [D, COUT]
    float* out = (float*)d_out;                 // [B, N, COUT]

    const int SSMEM = 4 * NNODES * 4;           // 64000 B
    cudaFuncSetAttribute(supports_kernel, cudaFuncAttributeMaxDynamicSharedMemorySize, SSMEM);
    cudaFuncSetAttribute(gemm_mma<0>, cudaFuncAttributeMaxDynamicSharedMemorySize, GSMEM);
    cudaFuncSetAttribute(gemm_mma<1>, cudaFuncAttributeMaxDynamicSharedMemorySize, GSMEM);
    cudaFuncSetAttribute(final_kernel, cudaFuncAttributeMaxDynamicSharedMemorySize, FSMEM);

    supports_kernel<<<NNODES / 4, 256, SSMEM>>>(emb);
    transpose_kernel<<<dim3(32, BATCH), 256>>>(x);

    dim3 g(32, 32);                             // Mtiles x Ntiles
    gemm_mma<0><<<g, 256, GSMEM>>>();           // y1 = S @ x   (-> y1n, y1th)
    gemm_mma<1><<<g, 256, GSMEM>>>();           // y2 = S @ y1  (-> y2n)

    final_kernel<<<NNODES / 2, 256, FSMEM>>>(x, emb, wp, bp, out);
}

// round 14
// speedup vs baseline: 1.3955x; 1.2205x over previous
#include <cuda_runtime.h>
#include <cuda_fp16.h>
#include <cstdint>

#define NNODES 4000
#define NPAD   4096
#define BATCH  64
#define CIN    64
#define COUT   64
#define EMBD   10
#define JDIM   4096            // BATCH * CIN
#define KTILES 125             // 4000 / 32
#define BM     128
#define BN     128
#define BK     32              // halves per k-tile
#define PADHB  80              // smem row stride in BYTES (64B data + 16B pad)
#define A_STG  (BM * PADHB)    // 10240 B
#define STAGE_BYTES ((BM + BN) * PADHB)     // 20480 B
#define NSTAGE 5
#define GSMEM  (NSTAGE * STAGE_BYTES)       // 102400 B

// ---- final_kernel smem layout (bytes), 4 nodes / 512 threads ----
#define KF      192            // 3 * CIN
#define W_ROWB  144            // W row stride: 128B data + 16B pad
#define W_NODE  (KF * W_ROWB)          // 27648
#define XG_ROWB 400            // Xg row stride: 384B data + 16B pad
#define XG_NODE (BATCH * XG_ROWB)      // 25600
#define W_OFF   0
#define XG_OFF  (4 * W_NODE)           // 110592
#define BIAS_OFF (XG_OFF + 4 * XG_NODE)  // 212992
#define EN_OFF  (BIAS_OFF + 4 * 64 * 4)  // 214016
#define FSMEM   (EN_OFF + 4 * EMBD * 4)  // 214176

// Scratch (allocation-free rule: __device__ globals; zero-initialized at load)
__device__ __half g_Sh  [(size_t)NPAD * NNODES];   // rows 4000..4095 stay zero
__device__ __half g_Xth [(size_t)JDIM * NNODES];   // x transposed fp16
__device__ __half g_y1th[(size_t)JDIM * NNODES];   // y1 transposed fp16 (B of GEMM2)
__device__ __half g_y1nh[(size_t)BATCH * NNODES * CIN];   // y1 normal fp16
__device__ __half g_y2nh[(size_t)BATCH * NNODES * CIN];   // y2 normal fp16

// ---------------------------------------------------------------------------
// helpers
// ---------------------------------------------------------------------------
__device__ __forceinline__ uint32_t smem_u32(const void* p) {
    uint32_t a;
    asm("{ .reg .u64 t; cvta.to.shared.u64 t, %1; cvt.u32.u64 %0, t; }" : "=r"(a) : "l"(p));
    return a;
}
__device__ __forceinline__ void cp16(uint32_t dst, const void* src) {
    asm volatile("cp.async.cg.shared.global [%0], [%1], 16;" :: "r"(dst), "l"(src) : "memory");
}
#define CP_COMMIT() asm volatile("cp.async.commit_group;" ::: "memory")
#define CP_WAIT3()  asm volatile("cp.async.wait_group 3;" ::: "memory")

#define LDSM4(R, A) \
    asm volatile("ldmatrix.sync.aligned.m8n8.x4.shared.b16 {%0,%1,%2,%3}, [%4];" \
        : "=r"((R)[0]), "=r"((R)[1]), "=r"((R)[2]), "=r"((R)[3]) : "r"(A))
#define LDSM4T(R, A) \
    asm volatile("ldmatrix.sync.aligned.m8n8.x4.trans.shared.b16 {%0,%1,%2,%3}, [%4];" \
        : "=r"((R)[0]), "=r"((R)[1]), "=r"((R)[2]), "=r"((R)[3]) : "r"(A))

__device__ __forceinline__ void mma_f16(float* c, const uint32_t* a,
                                        uint32_t b0, uint32_t b1) {
    asm volatile(
        "mma.sync.aligned.m16n8k16.row.col.f32.f16.f16.f32 "
        "{%0,%1,%2,%3}, {%4,%5,%6,%7}, {%8,%9}, {%0,%1,%2,%3};"
        : "+f"(c[0]), "+f"(c[1]), "+f"(c[2]), "+f"(c[3])
        : "r"(a[0]), "r"(a[1]), "r"(a[2]), "r"(a[3]), "r"(b0), "r"(b1));
}

union H2U { __half2 h; uint32_t u; };
__device__ __forceinline__ uint2 f4_to_h4(float a, float b, float c, float d) {
    H2U lo, hi;
    lo.h = __floats2half2_rn(a, b);
    hi.h = __floats2half2_rn(c, d);
    return make_uint2(lo.u, hi.u);
}

// ---------------------------------------------------------------------------
// Kernel 1: S = softmax(relu(E E^T), axis=1) -> fp16. 4 rows per block.
// ---------------------------------------------------------------------------
__global__ __launch_bounds__(256) void supports_kernel(const float* __restrict__ emb) {
    extern __shared__ float ssm[];          // logits[4][NNODES]
    __shared__ float en4[4][EMBD];
    __shared__ float red4[4][256];
    const int n0 = blockIdx.x * 4;
    const int t = threadIdx.x;
    if (t < 4 * EMBD) en4[t / EMBD][t % EMBD] = emb[(n0 + t / EMBD) * EMBD + (t % EMBD)];
    __syncthreads();

    float lmax[4] = {0.f, 0.f, 0.f, 0.f};
    for (int m = t; m < NNODES; m += 256) {
        float em[EMBD];
        #pragma unroll
        for (int i = 0; i < EMBD; i++) em[i] = emb[m * EMBD + i];
        #pragma unroll
        for (int r = 0; r < 4; r++) {
            float d = 0.f;
            #pragma unroll
            for (int i = 0; i < EMBD; i++) d += en4[r][i] * em[i];
            d = fmaxf(d, 0.f);
            ssm[r * NNODES + m] = d;
            lmax[r] = fmaxf(lmax[r], d);
        }
    }
    #pragma unroll
    for (int r = 0; r < 4; r++) red4[r][t] = lmax[r];
    __syncthreads();
    for (int s = 128; s > 0; s >>= 1) {
        if (t < s)
            #pragma unroll
            for (int r = 0; r < 4; r++) red4[r][t] = fmaxf(red4[r][t], red4[r][t + s]);
        __syncthreads();
    }
    float mx[4];
    #pragma unroll
    for (int r = 0; r < 4; r++) mx[r] = red4[r][0];
    __syncthreads();

    float lsum[4] = {0.f, 0.f, 0.f, 0.f};
    for (int m = t; m < NNODES; m += 256) {
        #pragma unroll
        for (int r = 0; r < 4; r++) {
            float e = __expf(ssm[r * NNODES + m] - mx[r]);
            ssm[r * NNODES + m] = e;
            lsum[r] += e;
        }
    }
    #pragma unroll
    for (int r = 0; r < 4; r++) red4[r][t] = lsum[r];
    __syncthreads();
    for (int s = 128; s > 0; s >>= 1) {
        if (t < s)
            #pragma unroll
            for (int r = 0; r < 4; r++) red4[r][t] += red4[r][t + s];
        __syncthreads();
    }
    float inv[4];
    #pragma unroll
    for (int r = 0; r < 4; r++) inv[r] = 1.0f / red4[r][0];

    for (int m = t; m < NNODES; m += 256) {
        #pragma unroll
        for (int r = 0; r < 4; r++)
            g_Sh[(size_t)(n0 + r) * NNODES + m] = __float2half_rn(ssm[r * NNODES + m] * inv[r]);
    }
}

// ---------------------------------------------------------------------------
// Kernel 2: transpose x[b,m,c] -> Xth[(b*64+c), m] fp16
// ---------------------------------------------------------------------------
__global__ __launch_bounds__(256) void transpose_kernel(const float* __restrict__ x) {
    __shared__ float Ts[128][68];
    const int t  = threadIdx.x;
    const int m0 = blockIdx.x * 128;
    const int b  = blockIdx.y;

    #pragma unroll
    for (int i = 0; i < 8; i++) {
        const int idx = t + 256 * i;
        const int row = idx >> 4, c4 = idx & 15;
        float4 v = make_float4(0.f, 0.f, 0.f, 0.f);
        if (m0 + row < NNODES)
            v = *(const float4*)&x[((size_t)b * NNODES + m0 + row) * CIN + c4 * 4];
        *(float4*)&Ts[row][c4 * 4] = v;
    }
    __syncthreads();

    #pragma unroll
    for (int i = 0; i < 8; i++) {
        const int o  = t + 256 * i;
        const int c  = o >> 5, mk = o & 31;
        const int m  = m0 + mk * 4;
        if (m + 3 < NNODES) {
            __half2 p0 = __floats2half2_rn(Ts[mk*4+0][c], Ts[mk*4+1][c]);
            __half2 p1 = __floats2half2_rn(Ts[mk*4+2][c], Ts[mk*4+3][c]);
            __half* dst = &g_Xth[(size_t)(b * 64 + c) * NNODES + m];
            *(__half2*)(dst)     = p0;
            *(__half2*)(dst + 2) = p1;
        }
    }
}

// ---------------------------------------------------------------------------
// Kernel 3: fp16 mma.sync GEMM  C[128,128] = S_tile[128,4000] @ B_tile^T
//   PHASE 0: B = Xth,  outputs y1nh (fp16 normal) + y1th (transposed)
//   PHASE 1: B = y1th, outputs y2nh (fp16 normal)
// ---------------------------------------------------------------------------
template <int PHASE>
__global__ __launch_bounds__(256, 2) void gemm_mma() {
    extern __shared__ char sm[];
    const uint32_t sBase = smem_u32(sm);

    const __half* __restrict__ Bmat = (PHASE == 0) ? g_Xth : g_y1th;
    const int m0 = blockIdx.x * BM;
    const int j0 = blockIdx.y * BN;

    const int t    = threadIdx.x;
    const int lane = t & 31, warp = t >> 5;
    const int wm = warp >> 2, wn = warp & 3;
    const int g = lane >> 2, tig = lane & 3;

    const int lr = t >> 2, lq = t & 3;

    const uint32_t aOff = (uint32_t)((wm * 64 + (lane & 7) + ((lane >> 3) & 1) * 8) * PADHB
                                     + ((lane >> 4) & 1) * 16);
    const uint32_t bOff = (uint32_t)(A_STG
                                     + (wn * 32 + (lane & 7) + ((lane >> 4) & 1) * 8) * PADHB
                                     + ((lane >> 3) & 1) * 16);

    float acc[4][4][4];
    #pragma unroll
    for (int mi = 0; mi < 4; mi++)
        #pragma unroll
        for (int ni = 0; ni < 4; ni++)
            #pragma unroll
            for (int q = 0; q < 4; q++) acc[mi][ni][q] = 0.f;

    auto load_tile = [&](int kt, int s) {
        const size_t kc = (size_t)kt * BK;
        const uint32_t st = sBase + s * STAGE_BYTES;
        #pragma unroll
        for (int i = 0; i < 2; i++) {
            const int r = lr + 64 * i;
            cp16(st + r * PADHB + lq * 16,
                 g_Sh + (size_t)(m0 + r) * NNODES + kc + lq * 8);
            cp16(st + A_STG + r * PADHB + lq * 16,
                 Bmat + (size_t)(j0 + r) * NNODES + kc + lq * 8);
        }
    };

    load_tile(0, 0); CP_COMMIT();
    load_tile(1, 1); CP_COMMIT();
    load_tile(2, 2); CP_COMMIT();
    load_tile(3, 3); CP_COMMIT();

    int sc = 0, sl = 4;
    for (int kt = 0; kt < KTILES; ++kt) {
        CP_WAIT3();
        __syncthreads();

        const uint32_t st = sBase + sc * STAGE_BYTES;
        {   // k16 = 0: LDSM, then next gmem loads, then MMA
            uint32_t a[4][4], b[2][4];
            #pragma unroll
            for (int mi = 0; mi < 4; mi++)
                LDSM4(a[mi], st + aOff + mi * (16 * PADHB));
            LDSM4(b[0], st + bOff);
            LDSM4(b[1], st + bOff + 16 * PADHB);

            if (kt + 4 < KTILES) load_tile(kt + 4, sl);
            CP_COMMIT();

            #pragma unroll
            for (int mi = 0; mi < 4; mi++) {
                mma_f16(acc[mi][0], a[mi], b[0][0], b[0][1]);
                mma_f16(acc[mi][1], a[mi], b[0][2], b[0][3]);
                mma_f16(acc[mi][2], a[mi], b[1][0], b[1][1]);
                mma_f16(acc[mi][3], a[mi], b[1][2], b[1][3]);
            }
        }
        {   // k16 = 1
            uint32_t a[4][4], b[2][4];
            #pragma unroll
            for (int mi = 0; mi < 4; mi++)
                LDSM4(a[mi], st + aOff + mi * (16 * PADHB) + 32);
            LDSM4(b[0], st + bOff + 32);
            LDSM4(b[1], st + bOff + 16 * PADHB + 32);
            #pragma unroll
            for (int mi = 0; mi < 4; mi++) {
                mma_f16(acc[mi][0], a[mi], b[0][0], b[0][1]);
                mma_f16(acc[mi][1], a[mi], b[0][2], b[0][3]);
                mma_f16(acc[mi][2], a[mi], b[1][0], b[1][1]);
                mma_f16(acc[mi][3], a[mi], b[1][2], b[1][3]);
            }
        }

        if (++sc == NSTAGE) sc = 0;
        if (++sl == NSTAGE) sl = 0;
    }

    // ---- epilogue: fp16 normal layout (+ y1th transposed for GEMM2)
    __half* __restrict__ outn = (PHASE == 0) ? g_y1nh : g_y2nh;
    #pragma unroll
    for (int mi = 0; mi < 4; mi++) {
        const int m = m0 + wm * 64 + mi * 16 + g;
        #pragma unroll
        for (int ni = 0; ni < 4; ni++) {
            const float* c = acc[mi][ni];
            const int j = j0 + wn * 32 + ni * 8 + tig * 2;
            const int b = j >> 6, cc = j & 63;
            if (m < NNODES) {
                __half2 h01 = __floats2half2_rn(c[0], c[1]);
                *(__half2*)&outn[((size_t)b * NNODES + m) * CIN + cc] = h01;
                if (PHASE == 0) {
                    g_y1th[(size_t)j * NNODES + m]       = __low2half(h01);
                    g_y1th[(size_t)(j + 1) * NNODES + m] = __high2half(h01);
                }
            }
            const int m2 = m + 8;
            if (m2 < NNODES) {
                __half2 h23 = __floats2half2_rn(c[2], c[3]);
                *(__half2*)&outn[((size_t)b * NNODES + m2) * CIN + cc] = h23;
                if (PHASE == 0) {
                    g_y1th[(size_t)j * NNODES + m2]       = __low2half(h23);
                    g_y1th[(size_t)(j + 1) * NNODES + m2] = __high2half(h23);
                }
            }
        }
    }
}

// ---------------------------------------------------------------------------
// Kernel 4 (tensor-core): per node n: out[., n, .] = Xg[64b x 192ki] @ W[ki][o] + bias
//   Xg = [x | y1 | 2*y2 - x] fp16; W[k*64+i][o] = sum_d en[d] wp[d,k,i,o] fp16.
// 4 nodes per block, 512 threads (4 warps per node, warp = 16 batches x 64 o).
// W stored [ki][o]; B fragments via ldmatrix.trans. One sync, then pure MMA.
// ---------------------------------------------------------------------------
__global__ __launch_bounds__(512, 1) void final_kernel(const float* __restrict__ x,
                                                       const float* __restrict__ emb,
                                                       const float* __restrict__ wp,
                                                       const float* __restrict__ bp,
                                                       float* __restrict__ out) {
    extern __shared__ char smc[];
    const uint32_t sBase = smem_u32(smc);
    float* bias4 = (float*)(smc + BIAS_OFF);   // [4][64]
    float* en4   = (float*)(smc + EN_OFF);     // [4][10]

    const int t  = threadIdx.x;
    const int n0 = blockIdx.x * 4;

    if (t < 4 * EMBD) en4[t] = emb[(n0 + t / EMBD) * EMBD + (t % EMBD)];
    __syncthreads();
    if (t < 256) {
        const int nd = t >> 6, o = t & 63;
        float s = 0.f;
        #pragma unroll
        for (int d = 0; d < EMBD; d++) s += en4[nd * EMBD + d] * bp[d * COUT + o];
        bias4[nd * 64 + o] = s;
    }

    // ---- weight generation: W[nd][k*64+i][o] fp16, wp loads shared over 4 nodes
    #pragma unroll
    for (int k = 0; k < 3; k++) {
        #pragma unroll
        for (int j = 0; j < 2; j++) {
            const int q  = t + 512 * j;        // 0..1023
            const int i  = q >> 4;
            const int o4 = q & 15;             // o = o4*4 .. +3
            float4 w[4];
            #pragma unroll
            for (int nd = 0; nd < 4; nd++) w[nd] = make_float4(0.f, 0.f, 0.f, 0.f);
            #pragma unroll
            for (int d = 0; d < EMBD; d++) {
                const float4 wv = *(const float4*)&wp[(((d * 3 + k) * CIN + i) * COUT) + o4 * 4];
                #pragma unroll
                for (int nd = 0; nd < 4; nd++) {
                    const float ed = en4[nd * EMBD + d];
                    w[nd].x += ed * wv.x; w[nd].y += ed * wv.y;
                    w[nd].z += ed * wv.z; w[nd].w += ed * wv.w;
                }
            }
            #pragma unroll
            for (int nd = 0; nd < 4; nd++)
                *(uint2*)(smc + W_OFF + nd * W_NODE + (k * 64 + i) * W_ROWB + o4 * 8)
                    = f4_to_h4(w[nd].x, w[nd].y, w[nd].z, w[nd].w);
        }
    }

    // ---- Xg fill: [nd][b][192] fp16  (x | y1 | 2*y2 - x)
    #pragma unroll
    for (int j = 0; j < 8; j++) {
        const int q  = t + 512 * j;            // 0..4095
        const int nd = q >> 10;
        const int r  = q & 1023;
        const int b  = r >> 4;
        const int c4 = r & 15;
        const size_t goff = ((size_t)b * NNODES + n0 + nd) * CIN + c4 * 4;
        char* dst = smc + XG_OFF + nd * XG_NODE + b * XG_ROWB + c4 * 8;

        const float4 vx = *(const float4*)&x[goff];
        *(uint2*)dst = f4_to_h4(vx.x, vx.y, vx.z, vx.w);

        *(uint2*)(dst + 128) = *(const uint2*)&g_y1nh[goff];

        const uint2 y2u = *(const uint2*)&g_y2nh[goff];
        H2U lo, hi; lo.u = y2u.x; hi.u = y2u.y;
        *(uint2*)(dst + 256) = f4_to_h4(
            2.f * __low2float(lo.h)  - vx.x, 2.f * __high2float(lo.h) - vx.y,
            2.f * __low2float(hi.h)  - vx.z, 2.f * __high2float(hi.h) - vx.w);
    }
    __syncthreads();

    // ---- MMA: warp handles 16 batches x 64 outputs over K=192
    const int lane = t & 31, warp = t >> 5;
    const int node = warp >> 2;
    const int mbase = (warp & 3) * 16;
    const int g = lane >> 2, tig = lane & 3;

    const uint32_t xgB = sBase + XG_OFF + node * XG_NODE + (mbase + (lane & 15)) * XG_ROWB
                       + ((lane >> 4) & 1) * 16;
    const uint32_t wB  = sBase + W_OFF + node * W_NODE
                       + ((lane & 7) + ((lane >> 3) & 1) * 8) * W_ROWB
                       + ((lane >> 4) & 1) * 16;

    float acc[8][4];
    #pragma unroll
    for (int ni = 0; ni < 8; ni++)
        #pragma unroll
        for (int q = 0; q < 4; q++) acc[ni][q] = 0.f;

    #pragma unroll
    for (int s = 0; s < 12; s++) {
        uint32_t a[4];
        LDSM4(a, xgB + s * 32);
        #pragma unroll
        for (int nb = 0; nb < 4; nb++) {
            uint32_t b[4];
            LDSM4T(b, wB + s * (16 * W_ROWB) + nb * 32);
            mma_f16(acc[nb * 2 + 0], a, b[0], b[1]);
            mma_f16(acc[nb * 2 + 1], a, b[2], b[3]);
        }
    }

    // ---- epilogue: add bias, store fp32 out
    const int nGlob = n0 + node;
    #pragma unroll
    for (int ni = 0; ni < 8; ni++) {
        const int o = ni * 8 + tig * 2;
        const float b0 = bias4[node * 64 + o];
        const float b1 = bias4[node * 64 + o + 1];
        const int r0 = mbase + g, r1 = r0 + 8;
        *(float2*)&out[((size_t)r0 * NNODES + nGlob) * COUT + o]
            = make_float2(acc[ni][0] + b0, acc[ni][1] + b1);
        *(float2*)&out[((size_t)r1 * NNODES + nGlob) * COUT + o]
            = make_float2(acc[ni][2] + b0, acc[ni][3] + b1);
    }
}

// ---------------------------------------------------------------------------
extern "C" void kernel_launch(void* const* d_in, const int* in_sizes, int n_in,
                              void* d_out, int out_size) {
    const float* x   = (const float*)d_in[0];   // [B, N, CIN]
    const float* emb = (const float*)d_in[1];   // [N, D]
    const float* wp  = (const float*)d_in[2];   // [D, K, CIN, COUT]
    const float* bp  = (const float*)d_in[3];   // [D, COUT]
    float* out = (float*)d_out;                 // [B, N, COUT]

    const int SSMEM = 4 * NNODES * 4;           // 64000 B
    cudaFuncSetAttribute(supports_kernel, cudaFuncAttributeMaxDynamicSharedMemorySize, SSMEM);
    cudaFuncSetAttribute(gemm_mma<0>, cudaFuncAttributeMaxDynamicSharedMemorySize, GSMEM);
    cudaFuncSetAttribute(gemm_mma<1>, cudaFuncAttributeMaxDynamicSharedMemorySize, GSMEM);
    cudaFuncSetAttribute(final_kernel, cudaFuncAttributeMaxDynamicSharedMemorySize, FSMEM);

    supports_kernel<<<NNODES / 4, 256, SSMEM>>>(emb);
    transpose_kernel<<<dim3(32, BATCH), 256>>>(x);

    dim3 g(32, 32);                             // Mtiles x Ntiles
    gemm_mma<0><<<g, 256, GSMEM>>>();           // y1 = S @ x   (-> y1nh, y1th)
    gemm_mma<1><<<g, 256, GSMEM>>>();           // y2 = S @ y1  (-> y2nh)

    final_kernel<<<NNODES / 4, 512, FSMEM>>>(x, emb, wp, bp, out);
}

// round 16
// speedup vs baseline: 1.4737x; 1.0560x over previous
#include <cuda_runtime.h>
#include <cuda_fp16.h>
#include <cstdint>

#define NNODES 4000
#define NPAD   4096
#define BATCH  64
#define CIN    64
#define COUT   64
#define EMBD   10
#define JDIM   4096            // BATCH * CIN
#define KTILES 125             // 4000 / 32
#define BM     128
#define BN     128
#define BK     32              // K-rows per tile
#define PADHB  80              // A smem row stride bytes (64B data + 16B pad)
#define B_ROWB 272             // B smem row stride bytes (256B data + 16B pad)
#define A_STG  (BM * PADHB)    // 10240 B
#define B_STG  (BK * B_ROWB)   // 8704 B
#define STAGE_BYTES (A_STG + B_STG)      // 18944 B
#define NSTAGE 5
#define GSMEM  (NSTAGE * STAGE_BYTES)    // 94720 B

// ---- final_kernel smem layout (bytes), 4 nodes / 512 threads ----
#define KF      192            // 3 * CIN
#define W_ROWB  144            // W row stride: 128B data + 16B pad
#define W_NODE  (KF * W_ROWB)          // 27648
#define XG_ROWB 400            // Xg row stride: 384B data + 16B pad
#define XG_NODE (BATCH * XG_ROWB)      // 25600
#define W_OFF   0
#define XG_OFF  (4 * W_NODE)           // 110592
#define BIAS_OFF (XG_OFF + 4 * XG_NODE)  // 212992
#define EN_OFF  (BIAS_OFF + 4 * 64 * 4)  // 214016
#define FSMEM   (EN_OFF + 4 * EMBD * 4)  // 214176

// Scratch (allocation-free rule: __device__ globals; zero-initialized at load)
__device__ __half g_Sh  [(size_t)NPAD * NNODES];   // rows 4000..4095 stay zero
__device__ __half g_xnh [(size_t)BATCH * NNODES * CIN];   // x normal fp16
__device__ __half g_y1nh[(size_t)BATCH * NNODES * CIN];   // y1 normal fp16
__device__ __half g_y2nh[(size_t)BATCH * NNODES * CIN];   // y2 normal fp16

// ---------------------------------------------------------------------------
// helpers
// ---------------------------------------------------------------------------
__device__ __forceinline__ uint32_t smem_u32(const void* p) {
    uint32_t a;
    asm("{ .reg .u64 t; cvta.to.shared.u64 t, %1; cvt.u32.u64 %0, t; }" : "=r"(a) : "l"(p));
    return a;
}
__device__ __forceinline__ void cp16(uint32_t dst, const void* src) {
    asm volatile("cp.async.cg.shared.global [%0], [%1], 16;" :: "r"(dst), "l"(src) : "memory");
}
#define CP_COMMIT() asm volatile("cp.async.commit_group;" ::: "memory")
#define CP_WAIT1()  asm volatile("cp.async.wait_group 1;" ::: "memory")

#define LDSM4(R, A) \
    asm volatile("ldmatrix.sync.aligned.m8n8.x4.shared.b16 {%0,%1,%2,%3}, [%4];" \
        : "=r"((R)[0]), "=r"((R)[1]), "=r"((R)[2]), "=r"((R)[3]) : "r"(A))
#define LDSM4T(R, A) \
    asm volatile("ldmatrix.sync.aligned.m8n8.x4.trans.shared.b16 {%0,%1,%2,%3}, [%4];" \
        : "=r"((R)[0]), "=r"((R)[1]), "=r"((R)[2]), "=r"((R)[3]) : "r"(A))

__device__ __forceinline__ void mma_f16(float* c, const uint32_t* a,
                                        uint32_t b0, uint32_t b1) {
    asm volatile(
        "mma.sync.aligned.m16n8k16.row.col.f32.f16.f16.f32 "
        "{%0,%1,%2,%3}, {%4,%5,%6,%7}, {%8,%9}, {%0,%1,%2,%3};"
        : "+f"(c[0]), "+f"(c[1]), "+f"(c[2]), "+f"(c[3])
        : "r"(a[0]), "r"(a[1]), "r"(a[2]), "r"(a[3]), "r"(b0), "r"(b1));
}

union H2U { __half2 h; uint32_t u; };
__device__ __forceinline__ uint2 f4_to_h4(float a, float b, float c, float d) {
    H2U lo, hi;
    lo.h = __floats2half2_rn(a, b);
    hi.h = __floats2half2_rn(c, d);
    return make_uint2(lo.u, hi.u);
}

// ---------------------------------------------------------------------------
// Kernel 1: S = softmax(relu(E E^T), axis=1) -> fp16. 4 rows per block.
// ---------------------------------------------------------------------------
__global__ __launch_bounds__(256) void supports_kernel(const float* __restrict__ emb) {
    extern __shared__ float ssm[];          // logits[4][NNODES]
    __shared__ float en4[4][EMBD];
    __shared__ float red4[4][256];
    const int n0 = blockIdx.x * 4;
    const int t = threadIdx.x;
    if (t < 4 * EMBD) en4[t / EMBD][t % EMBD] = emb[(n0 + t / EMBD) * EMBD + (t % EMBD)];
    __syncthreads();

    float lmax[4] = {0.f, 0.f, 0.f, 0.f};
    for (int m = t; m < NNODES; m += 256) {
        float em[EMBD];
        #pragma unroll
        for (int i = 0; i < EMBD; i++) em[i] = emb[m * EMBD + i];
        #pragma unroll
        for (int r = 0; r < 4; r++) {
            float d = 0.f;
            #pragma unroll
            for (int i = 0; i < EMBD; i++) d += en4[r][i] * em[i];
            d = fmaxf(d, 0.f);
            ssm[r * NNODES + m] = d;
            lmax[r] = fmaxf(lmax[r], d);
        }
    }
    #pragma unroll
    for (int r = 0; r < 4; r++) red4[r][t] = lmax[r];
    __syncthreads();
    for (int s = 128; s > 0; s >>= 1) {
        if (t < s)
            #pragma unroll
            for (int r = 0; r < 4; r++) red4[r][t] = fmaxf(red4[r][t], red4[r][t + s]);
        __syncthreads();
    }
    float mx[4];
    #pragma unroll
    for (int r = 0; r < 4; r++) mx[r] = red4[r][0];
    __syncthreads();

    float lsum[4] = {0.f, 0.f, 0.f, 0.f};
    for (int m = t; m < NNODES; m += 256) {
        #pragma unroll
        for (int r = 0; r < 4; r++) {
            float e = __expf(ssm[r * NNODES + m] - mx[r]);
            ssm[r * NNODES + m] = e;
            lsum[r] += e;
        }
    }
    #pragma unroll
    for (int r = 0; r < 4; r++) red4[r][t] = lsum[r];
    __syncthreads();
    for (int s = 128; s > 0; s >>= 1) {
        if (t < s)
            #pragma unroll
            for (int r = 0; r < 4; r++) red4[r][t] += red4[r][t + s];
        __syncthreads();
    }
    float inv[4];
    #pragma unroll
    for (int r = 0; r < 4; r++) inv[r] = 1.0f / red4[r][0];

    for (int m = t; m < NNODES; m += 256) {
        #pragma unroll
        for (int r = 0; r < 4; r++)
            g_Sh[(size_t)(n0 + r) * NNODES + m] = __float2half_rn(ssm[r * NNODES + m] * inv[r]);
    }
}

// ---------------------------------------------------------------------------
// Kernel 2: convert x fp32 -> xnh fp16 (same [b][m][c] layout)
// ---------------------------------------------------------------------------
__global__ __launch_bounds__(256) void convert_kernel(const float* __restrict__ x) {
    const int idx0 = (blockIdx.x * 256 + threadIdx.x) * 4;
    #pragma unroll
    for (int i = 0; i < 4; i++) {
        const size_t idx = (size_t)idx0 + i;   // float4 index; 4,096,000 total exact
        const float4 v = *(const float4*)&x[idx * 4];
        *(uint2*)&g_xnh[idx * 4] = f4_to_h4(v.x, v.y, v.z, v.w);
    }
}

// ---------------------------------------------------------------------------
// Kernel 3: fp16 mma.sync GEMM  C[128,128] = S_tile @ B^T,  B from NORMAL
// layout [b][m][c] via ldmatrix.trans (rows m = K-dim, coalesced cp.async).
//   PHASE 0: B = xnh,  out = y1nh
//   PHASE 1: B = y1nh, out = y2nh
// 8 warps 2(M)x4(N), warp 64x32; 5-stage cp.async (one-ahead wait_group 1),
// __syncthreads every 2 k-tiles.
// ---------------------------------------------------------------------------
template <int PHASE>
__global__ __launch_bounds__(256, 2) void gemm_mma() {
    extern __shared__ char sm[];
    const uint32_t sBase = smem_u32(sm);

    const __half* __restrict__ Bmat = (PHASE == 0) ? g_xnh : g_y1nh;
    __half* __restrict__ outn       = (PHASE == 0) ? g_y1nh : g_y2nh;
    const int m0 = blockIdx.x * BM;
    const int j0 = blockIdx.y * BN;

    const int t    = threadIdx.x;
    const int lane = t & 31, warp = t >> 5;
    const int wm = warp >> 2, wn = warp & 3;
    const int g = lane >> 2, tig = lane & 3;

    // A x4 (row-major): r0=(row,kLo) r1=(row+8,kLo) r2=(row,kHi) r3=(row+8,kHi)
    const uint32_t aOff = (uint32_t)((wm * 64 + (lane & 7) + ((lane >> 3) & 1) * 8) * PADHB
                                     + ((lane >> 4) & 1) * 16);
    // B trans (rows = K): same recipe as final_kernel's W operand
    const uint32_t bOff = (uint32_t)(A_STG
                                     + ((lane & 7) + ((lane >> 3) & 1) * 8) * B_ROWB
                                     + ((lane >> 4) & 1) * 16
                                     + wn * 64);      // warp's 32-j chunk (64B)

    float acc[4][4][4];
    #pragma unroll
    for (int mi = 0; mi < 4; mi++)
        #pragma unroll
        for (int ni = 0; ni < 4; ni++)
            #pragma unroll
            for (int q = 0; q < 4; q++) acc[mi][ni][q] = 0.f;

    auto load_tile = [&](int kt, int s) {
        const uint32_t st = sBase + s * STAGE_BYTES;
        // A: 128 rows x 64B (512 chunks of 16B)
        #pragma unroll
        for (int i = 0; i < 2; i++) {
            const int q = t + 256 * i;
            const int row = q >> 2, c4 = q & 3;
            cp16(st + row * PADHB + c4 * 16,
                 g_Sh + (size_t)(m0 + row) * NNODES + (size_t)kt * BK + c4 * 8);
        }
        // B: 32 m-rows x 128 j (512 chunks of 16B); j -> (b = j>>6, c = j&63)
        #pragma unroll
        for (int i = 0; i < 2; i++) {
            const int q = t + 256 * i;
            const int row = q >> 4, c16 = q & 15;
            const int j = j0 + c16 * 8;
            cp16(st + A_STG + row * B_ROWB + c16 * 16,
                 Bmat + ((size_t)(j >> 6) * NNODES + kt * BK + row) * CIN + (j & 63));
        }
    };

    load_tile(0, 0); CP_COMMIT();
    load_tile(1, 1); CP_COMMIT();
    load_tile(2, 2); CP_COMMIT();

    int sc = 0, sl = 3;
    for (int kt = 0; kt < KTILES; ++kt) {
        CP_WAIT1();                       // one-ahead: groups <= kt+1 complete
        if ((kt & 1) == 0) __syncthreads();

        const uint32_t st = sBase + sc * STAGE_BYTES;
        {   // k16 = 0: LDSM, then next gmem loads, then MMA
            uint32_t a[4][4], b[2][4];
            #pragma unroll
            for (int mi = 0; mi < 4; mi++)
                LDSM4(a[mi], st + aOff + mi * (16 * PADHB));
            LDSM4T(b[0], st + bOff);
            LDSM4T(b[1], st + bOff + 32);

            if (kt + 3 < KTILES) load_tile(kt + 3, sl);
            CP_COMMIT();                  // uniform group count (empty groups OK)

            #pragma unroll
            for (int mi = 0; mi < 4; mi++) {
                mma_f16(acc[mi][0], a[mi], b[0][0], b[0][1]);
                mma_f16(acc[mi][1], a[mi], b[0][2], b[0][3]);
                mma_f16(acc[mi][2], a[mi], b[1][0], b[1][1]);
                mma_f16(acc[mi][3], a[mi], b[1][2], b[1][3]);
            }
        }
        {   // k16 = 1 (rows +16 in B, cols +32B in A)
            uint32_t a[4][4], b[2][4];
            #pragma unroll
            for (int mi = 0; mi < 4; mi++)
                LDSM4(a[mi], st + aOff + mi * (16 * PADHB) + 32);
            LDSM4T(b[0], st + bOff + 16 * B_ROWB);
            LDSM4T(b[1], st + bOff + 16 * B_ROWB + 32);
            #pragma unroll
            for (int mi = 0; mi < 4; mi++) {
                mma_f16(acc[mi][0], a[mi], b[0][0], b[0][1]);
                mma_f16(acc[mi][1], a[mi], b[0][2], b[0][3]);
                mma_f16(acc[mi][2], a[mi], b[1][0], b[1][1]);
                mma_f16(acc[mi][3], a[mi], b[1][2], b[1][3]);
            }
        }

        if (++sc == NSTAGE) sc = 0;
        if (++sl == NSTAGE) sl = 0;
    }

    // ---- epilogue: fp16 normal layout only
    #pragma unroll
    for (int mi = 0; mi < 4; mi++) {
        const int m = m0 + wm * 64 + mi * 16 + g;
        #pragma unroll
        for (int ni = 0; ni < 4; ni++) {
            const float* c = acc[mi][ni];
            const int j = j0 + wn * 32 + ni * 8 + tig * 2;
            const int b = j >> 6, cc = j & 63;
            if (m < NNODES)
                *(__half2*)&outn[((size_t)b * NNODES + m) * CIN + cc]
                    = __floats2half2_rn(c[0], c[1]);
            const int m2 = m + 8;
            if (m2 < NNODES)
                *(__half2*)&outn[((size_t)b * NNODES + m2) * CIN + cc]
                    = __floats2half2_rn(c[2], c[3]);
        }
    }
}

// ---------------------------------------------------------------------------
// Kernel 4 (tensor-core): per node n: out = Xg[64b x 192ki] @ W[ki][o] + bias
// ---------------------------------------------------------------------------
__global__ __launch_bounds__(512, 1) void final_kernel(const float* __restrict__ x,
                                                       const float* __restrict__ emb,
                                                       const float* __restrict__ wp,
                                                       const float* __restrict__ bp,
                                                       float* __restrict__ out) {
    extern __shared__ char smc[];
    const uint32_t sBase = smem_u32(smc);
    float* bias4 = (float*)(smc + BIAS_OFF);   // [4][64]
    float* en4   = (float*)(smc + EN_OFF);     // [4][10]

    const int t  = threadIdx.x;
    const int n0 = blockIdx.x * 4;

    if (t < 4 * EMBD) en4[t] = emb[(n0 + t / EMBD) * EMBD + (t % EMBD)];
    __syncthreads();
    if (t < 256) {
        const int nd = t >> 6, o = t & 63;
        float s = 0.f;
        #pragma unroll
        for (int d = 0; d < EMBD; d++) s += en4[nd * EMBD + d] * bp[d * COUT + o];
        bias4[nd * 64 + o] = s;
    }

    // ---- weight generation: W[nd][k*64+i][o] fp16, wp loads shared over 4 nodes
    #pragma unroll
    for (int k = 0; k < 3; k++) {
        #pragma unroll
        for (int j = 0; j < 2; j++) {
            const int q  = t + 512 * j;        // 0..1023
            const int i  = q >> 4;
            const int o4 = q & 15;
            float4 w[4];
            #pragma unroll
            for (int nd = 0; nd < 4; nd++) w[nd] = make_float4(0.f, 0.f, 0.f, 0.f);
            #pragma unroll
            for (int d = 0; d < EMBD; d++) {
                const float4 wv = *(const float4*)&wp[(((d * 3 + k) * CIN + i) * COUT) + o4 * 4];
                #pragma unroll
                for (int nd = 0; nd < 4; nd++) {
                    const float ed = en4[nd * EMBD + d];
                    w[nd].x += ed * wv.x; w[nd].y += ed * wv.y;
                    w[nd].z += ed * wv.z; w[nd].w += ed * wv.w;
                }
            }
            #pragma unroll
            for (int nd = 0; nd < 4; nd++)
                *(uint2*)(smc + W_OFF + nd * W_NODE + (k * 64 + i) * W_ROWB + o4 * 8)
                    = f4_to_h4(w[nd].x, w[nd].y, w[nd].z, w[nd].w);
        }
    }

    // ---- Xg fill: [nd][b][192] fp16  (x | y1 | 2*y2 - x)
    #pragma unroll
    for (int j = 0; j < 8; j++) {
        const int q  = t + 512 * j;            // 0..4095
        const int nd = q >> 10;
        const int r  = q & 1023;
        const int b  = r >> 4;
        const int c4 = r & 15;
        const size_t goff = ((size_t)b * NNODES + n0 + nd) * CIN + c4 * 4;
        char* dst = smc + XG_OFF + nd * XG_NODE + b * XG_ROWB + c4 * 8;

        const float4 vx = *(const float4*)&x[goff];
        *(uint2*)dst = f4_to_h4(vx.x, vx.y, vx.z, vx.w);

        *(uint2*)(dst + 128) = *(const uint2*)&g_y1nh[goff];

        const uint2 y2u = *(const uint2*)&g_y2nh[goff];
        H2U lo, hi; lo.u = y2u.x; hi.u = y2u.y;
        *(uint2*)(dst + 256) = f4_to_h4(
            2.f * __low2float(lo.h)  - vx.x, 2.f * __high2float(lo.h) - vx.y,
            2.f * __low2float(hi.h)  - vx.z, 2.f * __high2float(hi.h) - vx.w);
    }
    __syncthreads();

    // ---- MMA: warp handles 16 batches x 64 outputs over K=192
    const int lane = t & 31, warp = t >> 5;
    const int node = warp >> 2;
    const int mbase = (warp & 3) * 16;
    const int g = lane >> 2, tig = lane & 3;

    const uint32_t xgB = sBase + XG_OFF + node * XG_NODE + (mbase + (lane & 15)) * XG_ROWB
                       + ((lane >> 4) & 1) * 16;
    const uint32_t wB  = sBase + W_OFF + node * W_NODE
                       + ((lane & 7) + ((lane >> 3) & 1) * 8) * W_ROWB
                       + ((lane >> 4) & 1) * 16;

    float acc[8][4];
    #pragma unroll
    for (int ni = 0; ni < 8; ni++)
        #pragma unroll
        for (int q = 0; q < 4; q++) acc[ni][q] = 0.f;

    #pragma unroll
    for (int s = 0; s < 12; s++) {
        uint32_t a[4];
        LDSM4(a, xgB + s * 32);
        #pragma unroll
        for (int nb = 0; nb < 4; nb++) {
            uint32_t b[4];
            LDSM4T(b, wB + s * (16 * W_ROWB) + nb * 32);
            mma_f16(acc[nb * 2 + 0], a, b[0], b[1]);
            mma_f16(acc[nb * 2 + 1], a, b[2], b[3]);
        }
    }

    // ---- epilogue: add bias, store fp32 out
    const int nGlob = n0 + node;
    #pragma unroll
    for (int ni = 0; ni < 8; ni++) {
        const int o = ni * 8 + tig * 2;
        const float b0 = bias4[node * 64 + o];
        const float b1 = bias4[node * 64 + o + 1];
        const int r0 = mbase + g, r1 = r0 + 8;
        *(float2*)&out[((size_t)r0 * NNODES + nGlob) * COUT + o]
            = make_float2(acc[ni][0] + b0, acc[ni][1] + b1);
        *(float2*)&out[((size_t)r1 * NNODES + nGlob) * COUT + o]
            = make_float2(acc[ni][2] + b0, acc[ni][3] + b1);
    }
}

// ---------------------------------------------------------------------------
extern "C" void kernel_launch(void* const* d_in, const int* in_sizes, int n_in,
                              void* d_out, int out_size) {
    const float* x   = (const float*)d_in[0];   // [B, N, CIN]
    const float* emb = (const float*)d_in[1];   // [N, D]
    const float* wp  = (const float*)d_in[2];   // [D, K, CIN, COUT]
    const float* bp  = (const float*)d_in[3];   // [D, COUT]
    float* out = (float*)d_out;                 // [B, N, COUT]

    const int SSMEM = 4 * NNODES * 4;           // 64000 B
    cudaFuncSetAttribute(supports_kernel, cudaFuncAttributeMaxDynamicSharedMemorySize, SSMEM);
    cudaFuncSetAttribute(gemm_mma<0>, cudaFuncAttributeMaxDynamicSharedMemorySize, GSMEM);
    cudaFuncSetAttribute(gemm_mma<1>, cudaFuncAttributeMaxDynamicSharedMemorySize, GSMEM);
    cudaFuncSetAttribute(final_kernel, cudaFuncAttributeMaxDynamicSharedMemorySize, FSMEM);

    supports_kernel<<<NNODES / 4, 256, SSMEM>>>(emb);
    convert_kernel<<<4000, 256>>>(x);           // x -> xnh fp16

    dim3 g(32, 32);                             // Mtiles x Ntiles
    gemm_mma<0><<<g, 256, GSMEM>>>();           // y1 = S @ x   (-> y1nh)
    gemm_mma<1><<<g, 256, GSMEM>>>();           // y2 = S @ y1  (-> y2nh)

    final_kernel<<<NNODES / 4, 512, FSMEM>>>(x, emb, wp, bp, out);
}